// round 2
// baseline (speedup 1.0000x reference)
#include <cuda_runtime.h>

#define NN 50000
#define DD 128
#define EE 800000
#define TD 384
#define MAXDEG 48
#define CAP 64
#define BN_BLOCKS 512
#define BN_CHUNK 98
#define WPAD 132   // row stride (floats) for weight tiles in smem: 16B-aligned + conflict-free

// ---------------- scratch (static device memory; no allocations) ----------------
__device__ float g_X[NN * DD];                     // normalized features
__device__ float g_G[(size_t)NN * TD];             // X @ W_ih^T + b_ih
__device__ float g_Hn[NN * DD];                    // final GRU hidden
__device__ float g_part[2 * BN_BLOCKS * DD];       // BN partial sums / sumsq
__device__ float g_mu[DD];
__device__ float g_scale[DD];                      // rsqrt(var+eps)*gamma
__device__ int   g_deg[NN];
__device__ unsigned long long g_keys[(size_t)NN * CAP];
__device__ int   g_neigh[NN * MAXDEG];             // src of k-th incoming edge (edge order)
__device__ int   g_len[NN];                        // min(deg, 48)
__device__ int   g_order[NN];                      // nodes sorted by len descending
__device__ int   g_hist[MAXDEG + 1];
__device__ int   g_cursor[MAXDEG + 1];

// ---------------- BatchNorm ----------------
__global__ void bn_partial_k(const float* __restrict__ feat) {
    int b = blockIdx.x;           // 0..511
    int d = threadIdx.x;          // 0..127
    int r0 = b * BN_CHUNK;
    int r1 = r0 + BN_CHUNK; if (r1 > NN) r1 = NN;
    float s = 0.f, ss = 0.f;
    for (int r = r0; r < r1; r++) {
        float v = feat[(size_t)r * DD + d];
        s += v; ss += v * v;
    }
    g_part[b * DD + d] = s;
    g_part[BN_BLOCKS * DD + b * DD + d] = ss;
}

__global__ void bn_final_k(const float* __restrict__ gamma) {
    int d = threadIdx.x;
    float s = 0.f, ss = 0.f;
    for (int b = 0; b < BN_BLOCKS; b++) {
        s  += g_part[b * DD + d];
        ss += g_part[BN_BLOCKS * DD + b * DD + d];
    }
    float mu = s / (float)NN;
    float var = ss / (float)NN - mu * mu;
    g_mu[d] = mu;
    g_scale[d] = rsqrtf(var + 1e-5f) * gamma[d];
}

__global__ void normalize_k(const float* __restrict__ feat, const float* __restrict__ beta) {
    int idx = blockIdx.x * blockDim.x + threadIdx.x;   // over NN*DD/4
    if (idx >= NN * DD / 4) return;
    float4 f = ((const float4*)feat)[idx];
    int d = (idx * 4) & (DD - 1);
    float4 o;
    o.x = (f.x - g_mu[d + 0]) * g_scale[d + 0] + beta[d + 0];
    o.y = (f.y - g_mu[d + 1]) * g_scale[d + 1] + beta[d + 1];
    o.z = (f.z - g_mu[d + 2]) * g_scale[d + 2] + beta[d + 2];
    o.w = (f.w - g_mu[d + 3]) * g_scale[d + 3] + beta[d + 3];
    ((float4*)g_X)[idx] = o;
}

// ---------------- adjacency build ----------------
__global__ void clear_k() {
    int i = blockIdx.x * blockDim.x + threadIdx.x;
    if (i < NN) g_deg[i] = 0;
    if (i <= MAXDEG) g_hist[i] = 0;
}

// NOTE: src/dst are int32 (JAX x64 disabled -> jnp.int64 silently becomes int32)
__global__ void scatter_k(const int* __restrict__ src, const int* __restrict__ dst) {
    int e = blockIdx.x * blockDim.x + threadIdx.x;
    if (e >= EE) return;
    int d = dst[e];
    if ((unsigned)d >= NN) return;   // defense: degrade to wrong answer, not crash
    int slot = atomicAdd(&g_deg[d], 1);
    if (slot < CAP)
        g_keys[(size_t)d * CAP + slot] = ((unsigned long long)e << 32) | (unsigned)src[e];
}

// one warp per node: rank-sort its <=CAP keys by edge index, keep first 48
__global__ void nodesort_k() {
    __shared__ unsigned long long buf[8][CAP];
    int lane = threadIdx.x & 31;
    int w = threadIdx.x >> 5;
    int node = blockIdx.x * 8 + w;
    if (node >= NN) return;
    int deg = g_deg[node];
    int L = deg < CAP ? deg : CAP;
    if (lane < L)      buf[w][lane]      = g_keys[(size_t)node * CAP + lane];
    if (lane + 32 < L) buf[w][lane + 32] = g_keys[(size_t)node * CAP + lane + 32];
    __syncwarp();
    for (int m = 0; m < 2; m++) {
        int idx = lane + 32 * m;
        if (idx < L) {
            unsigned long long key = buf[w][idx];
            int rank = 0;
            for (int i = 0; i < L; i++) rank += (buf[w][i] < key);
            if (rank < MAXDEG)
                g_neigh[node * MAXDEG + rank] = (int)(unsigned)(key & 0xffffffffull);
        }
    }
    if (lane == 0) {
        int len = deg < MAXDEG ? deg : MAXDEG;
        g_len[node] = len;
        atomicAdd(&g_hist[len], 1);
    }
}

__global__ void scan_k() {
    // descending-length offsets
    int running = 0;
    for (int l = MAXDEG; l >= 0; l--) {
        g_cursor[l] = running;
        running += g_hist[l];
    }
}

__global__ void place_k() {
    int n = blockIdx.x * blockDim.x + threadIdx.x;
    if (n >= NN) return;
    int l = g_len[n];
    int pos = atomicAdd(&g_cursor[l], 1);
    g_order[pos] = n;
}

// ---------------- G = X @ W_ih^T + b_ih  (32-row x 384-col tile per block) ----------------
__global__ __launch_bounds__(256, 1) void gemm384_k(const float* __restrict__ W,
                                                    const float* __restrict__ bias) {
    extern __shared__ float sm[];
    float* W_s = sm;                    // [384][WPAD]
    float* A_s = sm + TD * WPAD;        // [32][128]
    int tid = threadIdx.x, tj = tid & 31, tn = tid >> 5;
    int r0 = blockIdx.x * 32;
    for (int idx = tid; idx < TD * DD; idx += 256) {
        int j = idx >> 7, k = idx & (DD - 1);
        W_s[j * WPAD + k] = W[idx];
    }
    for (int idx = tid; idx < 32 * DD; idx += 256) {
        int r = r0 + (idx >> 7);
        A_s[idx] = (r < NN) ? g_X[(size_t)r * DD + (idx & (DD - 1))] : 0.f;
    }
    __syncthreads();
    float acc[4][12];
#pragma unroll
    for (int q = 0; q < 12; q++) {
        float bq = bias[tj + 32 * q];
#pragma unroll
        for (int i = 0; i < 4; i++) acc[i][q] = bq;
    }
#pragma unroll
    for (int k = 0; k < DD; k += 4) {
        float4 w4[12];
#pragma unroll
        for (int q = 0; q < 12; q++)
            w4[q] = *(const float4*)&W_s[(tj + 32 * q) * WPAD + k];
#pragma unroll
        for (int i = 0; i < 4; i++) {
            float4 a = *(const float4*)&A_s[(4 * tn + i) * DD + k];
#pragma unroll
            for (int q = 0; q < 12; q++)
                acc[i][q] += a.x * w4[q].x + a.y * w4[q].y + a.z * w4[q].z + a.w * w4[q].w;
        }
    }
#pragma unroll
    for (int i = 0; i < 4; i++) {
        int r = r0 + 4 * tn + i;
        if (r < NN) {
#pragma unroll
            for (int q = 0; q < 12; q++)
                g_G[(size_t)r * TD + tj + 32 * q] = acc[i][q];
        }
    }
}

// ---------------- GRU recurrence: 32 nodes/block, 4 nodes/warp (exclusive) ----------------
__global__ __launch_bounds__(256, 1) void gru_k(const float* __restrict__ Whh,
                                                const float* __restrict__ bhh) {
    extern __shared__ float sm[];
    float* W_s = sm;                    // [384][WPAD]
    float* H_s = sm + TD * WPAD;        // [32][128]
    int*   meta = (int*)(H_s + 32 * DD); // nid[32], len[32]
    int tid = threadIdx.x, tj = tid & 31, tn = tid >> 5;
    int base = blockIdx.x * 32;

    for (int idx = tid; idx < TD * DD; idx += 256) {
        int j = idx >> 7, k = idx & (DD - 1);
        W_s[j * WPAD + k] = Whh[idx];
    }
    if (tid < 32) {
        int g = base + tid;
        int nid = (g < NN) ? g_order[g] : -1;
        meta[tid] = nid;
        meta[32 + tid] = (nid >= 0) ? g_len[nid] : 0;
    }
    for (int idx = tid; idx < 32 * DD; idx += 256) H_s[idx] = 0.f;
    float bh[12];
#pragma unroll
    for (int q = 0; q < 12; q++) bh[q] = bhh[tj + 32 * q];
    __syncthreads();

    int n0 = tn * 4;
    int nid[4], lenv[4], wmax = 0;
#pragma unroll
    for (int i = 0; i < 4; i++) {
        nid[i]  = meta[n0 + i];
        lenv[i] = meta[32 + n0 + i];
        wmax = lenv[i] > wmax ? lenv[i] : wmax;
    }

    for (int t = 0; t < wmax; t++) {
        float acc[4][12];
#pragma unroll
        for (int i = 0; i < 4; i++)
#pragma unroll
            for (int q = 0; q < 12; q++) acc[i][q] = bh[q];

#pragma unroll
        for (int k = 0; k < DD; k += 4) {
            float4 w4[12];
#pragma unroll
            for (int q = 0; q < 12; q++)
                w4[q] = *(const float4*)&W_s[(tj + 32 * q) * WPAD + k];
#pragma unroll
            for (int i = 0; i < 4; i++) {
                float4 a = *(const float4*)&H_s[(n0 + i) * DD + k];
#pragma unroll
                for (int q = 0; q < 12; q++)
                    acc[i][q] += a.x * w4[q].x + a.y * w4[q].y + a.z * w4[q].z + a.w * w4[q].w;
            }
        }
        __syncwarp();
#pragma unroll
        for (int i = 0; i < 4; i++) {
            if (t < lenv[i]) {
                int s = g_neigh[nid[i] * MAXDEG + t];
                const float* Gi = g_G + (size_t)s * TD;
#pragma unroll
                for (int p = 0; p < 4; p++) {
                    int d = tj + 32 * p;
                    float gr = Gi[d], gz = Gi[DD + d], gn = Gi[2 * DD + d];
                    float r  = __fdividef(1.f, 1.f + __expf(-(acc[i][p]     + gr)));
                    float z  = __fdividef(1.f, 1.f + __expf(-(acc[i][p + 4] + gz)));
                    float pre = gn + r * acc[i][p + 8];
                    float nn = 1.f - __fdividef(2.f, __expf(2.f * pre) + 1.f);
                    float ho = H_s[(n0 + i) * DD + d];
                    H_s[(n0 + i) * DD + d] = (1.f - z) * nn + z * ho;
                }
            }
        }
        __syncwarp();
    }

#pragma unroll
    for (int i = 0; i < 4; i++) {
        if (nid[i] >= 0) {
#pragma unroll
            for (int p = 0; p < 4; p++) {
                int d = tj + 32 * p;
                g_Hn[(size_t)nid[i] * DD + d] = H_s[(n0 + i) * DD + d];
            }
        }
    }
}

// ---------------- out = X @ W_self^T + Hn @ W_neigh^T ----------------
__global__ __launch_bounds__(256, 1) void out_k(const float* __restrict__ Wself,
                                                const float* __restrict__ Wneigh,
                                                float* __restrict__ out) {
    extern __shared__ float sm[];
    float* Ws_s = sm;                      // [128][WPAD]
    float* Wn_s = sm + DD * WPAD;          // [128][WPAD]
    float* Xs   = sm + 2 * DD * WPAD;      // [32][128]
    float* Hs   = Xs + 32 * DD;            // [32][128]
    int tid = threadIdx.x, tj = tid & 31, tn = tid >> 5;
    int r0 = blockIdx.x * 32;
    for (int idx = tid; idx < DD * DD; idx += 256) {
        int o = idx >> 7, k = idx & (DD - 1);
        Ws_s[o * WPAD + k] = Wself[idx];
        Wn_s[o * WPAD + k] = Wneigh[idx];
    }
    for (int idx = tid; idx < 32 * DD; idx += 256) {
        int r = r0 + (idx >> 7);
        int c = idx & (DD - 1);
        Xs[idx] = (r < NN) ? g_X [(size_t)r * DD + c] : 0.f;
        Hs[idx] = (r < NN) ? g_Hn[(size_t)r * DD + c] : 0.f;
    }
    __syncthreads();
    float acc[4][4];
#pragma unroll
    for (int i = 0; i < 4; i++)
#pragma unroll
        for (int q = 0; q < 4; q++) acc[i][q] = 0.f;
#pragma unroll
    for (int k = 0; k < DD; k += 4) {
        float4 ws[4], wn[4];
#pragma unroll
        for (int q = 0; q < 4; q++) {
            ws[q] = *(const float4*)&Ws_s[(tj + 32 * q) * WPAD + k];
            wn[q] = *(const float4*)&Wn_s[(tj + 32 * q) * WPAD + k];
        }
#pragma unroll
        for (int i = 0; i < 4; i++) {
            float4 x = *(const float4*)&Xs[(4 * tn + i) * DD + k];
            float4 h = *(const float4*)&Hs[(4 * tn + i) * DD + k];
#pragma unroll
            for (int q = 0; q < 4; q++) {
                acc[i][q] += x.x * ws[q].x + x.y * ws[q].y + x.z * ws[q].z + x.w * ws[q].w;
                acc[i][q] += h.x * wn[q].x + h.y * wn[q].y + h.z * wn[q].z + h.w * wn[q].w;
            }
        }
    }
#pragma unroll
    for (int i = 0; i < 4; i++) {
        int r = r0 + 4 * tn + i;
        if (r < NN) {
#pragma unroll
            for (int q = 0; q < 4; q++)
                out[(size_t)r * DD + tj + 32 * q] = acc[i][q];
        }
    }
}

// ---------------- launch ----------------
extern "C" void kernel_launch(void* const* d_in, const int* in_sizes, int n_in,
                              void* d_out, int out_size) {
    const float* feat   = (const float*)d_in[0];
    const int*   src    = (const int*)d_in[1];    // int32 (JAX x64 disabled)
    const int*   dst    = (const int*)d_in[2];    // int32
    const float* gamma  = (const float*)d_in[3];
    const float* beta   = (const float*)d_in[4];
    const float* W_ih   = (const float*)d_in[5];
    const float* W_hh   = (const float*)d_in[6];
    const float* b_ih   = (const float*)d_in[7];
    const float* b_hh   = (const float*)d_in[8];
    const float* W_self = (const float*)d_in[9];
    const float* W_neigh= (const float*)d_in[10];
    float* out = (float*)d_out;

    const int smA = (TD * WPAD + 32 * DD) * 4;           // gemm384
    const int smG = smA + 64 * 4;                        // gru (+meta)
    const int smO = (2 * DD * WPAD + 2 * 32 * DD) * 4;   // out
    cudaFuncSetAttribute(gemm384_k, cudaFuncAttributeMaxDynamicSharedMemorySize, smA);
    cudaFuncSetAttribute(gru_k,     cudaFuncAttributeMaxDynamicSharedMemorySize, smG);
    cudaFuncSetAttribute(out_k,     cudaFuncAttributeMaxDynamicSharedMemorySize, smO);

    const int NB = (NN + 31) / 32;   // 1563

    bn_partial_k<<<BN_BLOCKS, DD>>>(feat);
    bn_final_k<<<1, DD>>>(gamma);
    normalize_k<<<(NN * DD / 4 + 255) / 256, 256>>>(feat, beta);
    clear_k<<<(NN + 255) / 256, 256>>>();
    scatter_k<<<(EE + 255) / 256, 256>>>(src, dst);
    nodesort_k<<<(NN + 7) / 8, 256>>>();
    scan_k<<<1, 1>>>();
    place_k<<<(NN + 255) / 256, 256>>>();
    gemm384_k<<<NB, 256, smA>>>(W_ih, b_ih);
    gru_k<<<NB, 256, smG>>>(W_hh, b_hh);
    out_k<<<NB, 256, smO>>>(W_self, W_neigh, out);
}

// round 4
// speedup vs baseline: 3.0087x; 3.0087x over previous
#include <cuda_runtime.h>
#include <cstdint>

#define NN 50000
#define DD 128
#define EE 800000
#define TD 384
#define MAXDEG 48
#define CAP 64
#define BN_BLOCKS 512
#define BN_CHUNK 98
#define WPAD 132        // stride ≡ 4 (mod 32): conflict-free mma fragment LDS
#define GNODES 32
#define GRU_BLOCKS ((NN + GNODES - 1) / GNODES)   // 1563

// ---------------- scratch (static device memory; no allocations) ----------------
__device__ float g_X[NN * DD];
__device__ float g_G[(size_t)NN * TD];
__device__ float g_Hn[NN * DD];
__device__ float g_part[2 * BN_BLOCKS * DD];
__device__ float g_mu[DD];
__device__ float g_scale[DD];
__device__ int   g_deg[NN];
__device__ unsigned long long g_keys[(size_t)NN * CAP];
__device__ int   g_neigh[NN * MAXDEG];
__device__ int   g_len[NN];
__device__ int   g_order[NN];
__device__ int   g_hist[MAXDEG + 1];
__device__ int   g_cursor[MAXDEG + 1];

// ---------------- helpers ----------------
__device__ __forceinline__ float tf32r(float x) {
    uint32_t r;
    asm("cvt.rna.tf32.f32 %0, %1;" : "=r"(r) : "f"(x));
    return __uint_as_float(r);
}
__device__ __forceinline__ void mma8(float* c, const uint32_t* a, const uint32_t* b) {
    asm volatile(
        "mma.sync.aligned.m16n8k8.row.col.f32.tf32.tf32.f32 "
        "{%0,%1,%2,%3},{%4,%5,%6,%7},{%8,%9},{%0,%1,%2,%3};"
        : "+f"(c[0]), "+f"(c[1]), "+f"(c[2]), "+f"(c[3])
        : "r"(a[0]), "r"(a[1]), "r"(a[2]), "r"(a[3]), "r"(b[0]), "r"(b[1]));
}

// ---------------- BatchNorm ----------------
__global__ void bn_partial_k(const float* __restrict__ feat) {
    int b = blockIdx.x, d = threadIdx.x;
    int r0 = b * BN_CHUNK;
    int r1 = r0 + BN_CHUNK; if (r1 > NN) r1 = NN;
    float s = 0.f, ss = 0.f;
    for (int r = r0; r < r1; r++) {
        float v = feat[(size_t)r * DD + d];
        s += v; ss += v * v;
    }
    g_part[b * DD + d] = s;
    g_part[BN_BLOCKS * DD + b * DD + d] = ss;
}

__global__ void bn_final_k(const float* __restrict__ gamma) {
    int d = threadIdx.x;
    float s = 0.f, ss = 0.f;
    for (int b = 0; b < BN_BLOCKS; b++) {
        s  += g_part[b * DD + d];
        ss += g_part[BN_BLOCKS * DD + b * DD + d];
    }
    float mu = s / (float)NN;
    float var = ss / (float)NN - mu * mu;
    g_mu[d] = mu;
    g_scale[d] = rsqrtf(var + 1e-5f) * gamma[d];
}

__global__ void normalize_k(const float* __restrict__ feat, const float* __restrict__ beta) {
    int idx = blockIdx.x * blockDim.x + threadIdx.x;
    if (idx >= NN * DD / 4) return;
    float4 f = ((const float4*)feat)[idx];
    int d = (idx * 4) & (DD - 1);
    float4 o;
    o.x = (f.x - g_mu[d + 0]) * g_scale[d + 0] + beta[d + 0];
    o.y = (f.y - g_mu[d + 1]) * g_scale[d + 1] + beta[d + 1];
    o.z = (f.z - g_mu[d + 2]) * g_scale[d + 2] + beta[d + 2];
    o.w = (f.w - g_mu[d + 3]) * g_scale[d + 3] + beta[d + 3];
    ((float4*)g_X)[idx] = o;
}

// ---------------- adjacency build ----------------
__global__ void clear_k() {
    int i = blockIdx.x * blockDim.x + threadIdx.x;
    if (i < NN) g_deg[i] = 0;
    if (i <= MAXDEG) g_hist[i] = 0;
}

__global__ void scatter_k(const int* __restrict__ src, const int* __restrict__ dst) {
    int e = blockIdx.x * blockDim.x + threadIdx.x;
    if (e >= EE) return;
    int d = dst[e];
    if ((unsigned)d >= NN) return;
    int slot = atomicAdd(&g_deg[d], 1);
    if (slot < CAP)
        g_keys[(size_t)d * CAP + slot] = ((unsigned long long)e << 32) | (unsigned)src[e];
}

__global__ void nodesort_k() {
    __shared__ unsigned long long buf[8][CAP];
    int lane = threadIdx.x & 31;
    int w = threadIdx.x >> 5;
    int node = blockIdx.x * 8 + w;
    if (node >= NN) return;
    int deg = g_deg[node];
    int L = deg < CAP ? deg : CAP;
    if (lane < L)      buf[w][lane]      = g_keys[(size_t)node * CAP + lane];
    if (lane + 32 < L) buf[w][lane + 32] = g_keys[(size_t)node * CAP + lane + 32];
    __syncwarp();
    for (int m = 0; m < 2; m++) {
        int idx = lane + 32 * m;
        if (idx < L) {
            unsigned long long key = buf[w][idx];
            int rank = 0;
            for (int i = 0; i < L; i++) rank += (buf[w][i] < key);
            if (rank < MAXDEG)
                g_neigh[node * MAXDEG + rank] = (int)(unsigned)(key & 0xffffffffull);
        }
    }
    if (lane == 0) {
        int len = deg < MAXDEG ? deg : MAXDEG;
        g_len[node] = len;
        atomicAdd(&g_hist[len], 1);
    }
}

__global__ void scan_k() {
    int running = 0;
    for (int l = MAXDEG; l >= 0; l--) {
        g_cursor[l] = running;
        running += g_hist[l];
    }
}

__global__ void place_k() {
    int n = blockIdx.x * blockDim.x + threadIdx.x;
    if (n >= NN) return;
    int l = g_len[n];
    int pos = atomicAdd(&g_cursor[l], 1);
    g_order[pos] = n;
}

// ---------------- G = X @ W_ih^T + b_ih ----------------
__global__ __launch_bounds__(256, 1) void gemm384_k(const float* __restrict__ W,
                                                    const float* __restrict__ bias) {
    extern __shared__ float sm[];
    float* W_s = sm;
    float* A_s = sm + TD * WPAD;
    int tid = threadIdx.x, tj = tid & 31, tn = tid >> 5;
    int r0 = blockIdx.x * 32;
    for (int idx = tid; idx < TD * DD; idx += 256) {
        int j = idx >> 7, k = idx & (DD - 1);
        W_s[j * WPAD + k] = W[idx];
    }
    for (int idx = tid; idx < 32 * DD; idx += 256) {
        int r = r0 + (idx >> 7);
        A_s[idx] = (r < NN) ? g_X[(size_t)r * DD + (idx & (DD - 1))] : 0.f;
    }
    __syncthreads();
    float acc[4][12];
#pragma unroll
    for (int q = 0; q < 12; q++) {
        float bq = bias[tj + 32 * q];
#pragma unroll
        for (int i = 0; i < 4; i++) acc[i][q] = bq;
    }
#pragma unroll
    for (int k = 0; k < DD; k += 4) {
        float4 w4[12];
#pragma unroll
        for (int q = 0; q < 12; q++)
            w4[q] = *(const float4*)&W_s[(tj + 32 * q) * WPAD + k];
#pragma unroll
        for (int i = 0; i < 4; i++) {
            float4 a = *(const float4*)&A_s[(4 * tn + i) * DD + k];
#pragma unroll
            for (int q = 0; q < 12; q++)
                acc[i][q] += a.x * w4[q].x + a.y * w4[q].y + a.z * w4[q].z + a.w * w4[q].w;
        }
    }
#pragma unroll
    for (int i = 0; i < 4; i++) {
        int r = r0 + 4 * tn + i;
        if (r < NN) {
#pragma unroll
            for (int q = 0; q < 12; q++)
                g_G[(size_t)r * TD + tj + 32 * q] = acc[i][q];
        }
    }
}

// ---------------- GRU recurrence via mma.sync tf32 ----------------
// 32 sorted nodes / CTA, 256 threads (8 warps). Per step GEMM: M=32, N=384, K=128.
// Warp w owns output dims [16w, 16w+16) for all 3 gates (12 m16n8 C-tiles).
// W_hh in SMEM [384][WPAD], H (A operand, tf32) in SMEM [32][WPAD]; fp32 master H in regs.
__global__ __launch_bounds__(256, 1) void gru_mma_k(const float* __restrict__ Whh,
                                                    const float* __restrict__ bhh) {
    extern __shared__ float sm[];
    float* W_s = sm;                         // 384*WPAD
    float* H_s = sm + 384 * WPAD;            // 32*WPAD
    int*   s_s   = (int*)(H_s + 32 * WPAD);  // [2][32] double-buffered src ids
    int*   nid_s = s_s + 64;                 // [32]
    int*   len_s = nid_s + 32;               // [32]

    int tid = threadIdx.x, lane = tid & 31, w = tid >> 5;
    int g2 = lane >> 2, t4 = lane & 3;       // groupID, tid-in-group
    int dbase = w * 16;
    int base = blockIdx.x * GNODES;

    // prepack W_hh (tf32-rounded), zero H, load meta
    for (int i = tid; i < TD * DD; i += 256) {
        int n = i >> 7, k = i & 127;
        W_s[n * WPAD + k] = tf32r(Whh[i]);
    }
    for (int i = tid; i < 32 * WPAD; i += 256) H_s[i] = 0.f;
    if (tid < GNODES) {
        int gi = base + tid;
        int nid = (gi < NN) ? g_order[gi] : -1;
        nid_s[tid] = nid;
        len_s[tid] = (nid >= 0) ? g_len[nid] : 0;
    }
    __syncthreads();

    int maxlen = len_s[0];
    int lenR[2][2], nidR[2][2];
#pragma unroll
    for (int mt = 0; mt < 2; mt++)
#pragma unroll
        for (int rr = 0; rr < 2; rr++) {
            int r = 16 * mt + g2 + 8 * rr;
            lenR[mt][rr] = len_s[r];
            nidR[mt][rr] = nid_s[r];
        }
    float bb[3][2][2];
#pragma unroll
    for (int g = 0; g < 3; g++)
#pragma unroll
        for (int dt = 0; dt < 2; dt++) {
            int D0 = g * 128 + dbase + 8 * dt + 2 * t4;
            bb[g][dt][0] = bhh[D0];
            bb[g][dt][1] = bhh[D0 + 1];
        }
    float ho[2][2][4];                        // [mt][dt][rr*2+e] fp32 master hidden
#pragma unroll
    for (int mt = 0; mt < 2; mt++)
#pragma unroll
        for (int dt = 0; dt < 2; dt++)
#pragma unroll
            for (int c = 0; c < 4; c++) ho[mt][dt][c] = 0.f;

    // stage src ids for t=0
    if (tid < GNODES)
        s_s[tid] = (0 < len_s[tid]) ? g_neigh[nid_s[tid] * MAXDEG] : 0;
    __syncthreads();

    const uint32_t* Hs = (const uint32_t*)H_s;
    const uint32_t* Ws = (const uint32_t*)W_s;

    for (int t = 0; t < maxlen; t++) {
        // ---- prefetch G rows (hidden under the mma loop) ----
        float2 gf[2][2][2][3];                // [mt][rr][dt][gate]
#pragma unroll
        for (int mt = 0; mt < 2; mt++)
#pragma unroll
            for (int rr = 0; rr < 2; rr++) {
                int s = s_s[(t & 1) * 32 + 16 * mt + g2 + 8 * rr];
                const float* Gp = g_G + (size_t)s * TD;
#pragma unroll
                for (int dt = 0; dt < 2; dt++) {
                    int D0 = dbase + 8 * dt + 2 * t4;
#pragma unroll
                    for (int g = 0; g < 3; g++)
                        gf[mt][rr][dt][g] = *(const float2*)(Gp + g * 128 + D0);
                }
            }

        // ---- init accumulators with b_hh ----
        float cacc[3][2][2][4];               // [gate][mt][dt][4]
#pragma unroll
        for (int g = 0; g < 3; g++)
#pragma unroll
            for (int mt = 0; mt < 2; mt++)
#pragma unroll
                for (int dt = 0; dt < 2; dt++) {
                    cacc[g][mt][dt][0] = bb[g][dt][0];
                    cacc[g][mt][dt][1] = bb[g][dt][1];
                    cacc[g][mt][dt][2] = bb[g][dt][0];
                    cacc[g][mt][dt][3] = bb[g][dt][1];
                }

        // ---- mma K-loop ----
#pragma unroll
        for (int kk = 0; kk < 16; kk++) {
            int c0 = kk * 8 + t4;
            uint32_t am[2][4];
#pragma unroll
            for (int mt = 0; mt < 2; mt++) {
                int r0 = 16 * mt + g2;
                am[mt][0] = Hs[r0 * WPAD + c0];
                am[mt][1] = Hs[(r0 + 8) * WPAD + c0];
                am[mt][2] = Hs[r0 * WPAD + c0 + 4];
                am[mt][3] = Hs[(r0 + 8) * WPAD + c0 + 4];
            }
            uint32_t bf[3][2][2];
#pragma unroll
            for (int g = 0; g < 3; g++)
#pragma unroll
                for (int dt = 0; dt < 2; dt++) {
                    int n = g * 128 + dbase + 8 * dt + g2;
                    bf[g][dt][0] = Ws[n * WPAD + c0];
                    bf[g][dt][1] = Ws[n * WPAD + c0 + 4];
                }
#pragma unroll
            for (int g = 0; g < 3; g++)
#pragma unroll
                for (int mt = 0; mt < 2; mt++)
#pragma unroll
                    for (int dt = 0; dt < 2; dt++)
                        mma8(cacc[g][mt][dt], am[mt], bf[g][dt]);
        }
        __syncthreads();   // all H_s reads done

        // ---- epilogue: gates, update H ----
#pragma unroll
        for (int mt = 0; mt < 2; mt++)
#pragma unroll
            for (int rr = 0; rr < 2; rr++) {
                bool act = (t < lenR[mt][rr]);
                int R = 16 * mt + g2 + 8 * rr;
#pragma unroll
                for (int dt = 0; dt < 2; dt++) {
#pragma unroll
                    for (int e = 0; e < 2; e++) {
                        int c = rr * 2 + e;
                        float gr = e ? gf[mt][rr][dt][0].y : gf[mt][rr][dt][0].x;
                        float gz = e ? gf[mt][rr][dt][1].y : gf[mt][rr][dt][1].x;
                        float gn = e ? gf[mt][rr][dt][2].y : gf[mt][rr][dt][2].x;
                        float r  = __fdividef(1.f, 1.f + __expf(-(gr + cacc[0][mt][dt][c])));
                        float z  = __fdividef(1.f, 1.f + __expf(-(gz + cacc[1][mt][dt][c])));
                        float pre = gn + r * cacc[2][mt][dt][c];
                        float nl = 1.f - __fdividef(2.f, __expf(2.f * pre) + 1.f);
                        float hnew = (1.f - z) * nl + z * ho[mt][dt][c];
                        if (act) ho[mt][dt][c] = hnew;
                    }
                    int D0 = dbase + 8 * dt + 2 * t4;
                    *(float2*)&H_s[R * WPAD + D0] =
                        make_float2(tf32r(ho[mt][dt][rr * 2]), tf32r(ho[mt][dt][rr * 2 + 1]));
                }
            }
        // stage src ids for t+1
        if (tid < GNODES) {
            int tt = t + 1;
            s_s[(tt & 1) * 32 + tid] =
                (tt < len_s[tid]) ? g_neigh[nid_s[tid] * MAXDEG + tt] : 0;
        }
        __syncthreads();
    }

    // ---- final hidden to gmem ----
#pragma unroll
    for (int mt = 0; mt < 2; mt++)
#pragma unroll
        for (int rr = 0; rr < 2; rr++) {
            int nid = nidR[mt][rr];
            if (nid >= 0) {
#pragma unroll
                for (int dt = 0; dt < 2; dt++) {
                    int D0 = dbase + 8 * dt + 2 * t4;
                    *(float2*)&g_Hn[(size_t)nid * DD + D0] =
                        make_float2(ho[mt][dt][rr * 2], ho[mt][dt][rr * 2 + 1]);
                }
            }
        }
}

// ---------------- out = X @ W_self^T + Hn @ W_neigh^T ----------------
__global__ __launch_bounds__(256, 1) void out_k(const float* __restrict__ Wself,
                                                const float* __restrict__ Wneigh,
                                                float* __restrict__ out) {
    extern __shared__ float sm[];
    float* Ws_s = sm;
    float* Wn_s = sm + DD * WPAD;
    float* Xs   = sm + 2 * DD * WPAD;
    float* Hs   = Xs + 32 * DD;
    int tid = threadIdx.x, tj = tid & 31, tn = tid >> 5;
    int r0 = blockIdx.x * 32;
    for (int idx = tid; idx < DD * DD; idx += 256) {
        int o = idx >> 7, k = idx & (DD - 1);
        Ws_s[o * WPAD + k] = Wself[idx];
        Wn_s[o * WPAD + k] = Wneigh[idx];
    }
    for (int idx = tid; idx < 32 * DD; idx += 256) {
        int r = r0 + (idx >> 7);
        int c = idx & (DD - 1);
        Xs[idx] = (r < NN) ? g_X [(size_t)r * DD + c] : 0.f;
        Hs[idx] = (r < NN) ? g_Hn[(size_t)r * DD + c] : 0.f;
    }
    __syncthreads();
    float acc[4][4];
#pragma unroll
    for (int i = 0; i < 4; i++)
#pragma unroll
        for (int q = 0; q < 4; q++) acc[i][q] = 0.f;
#pragma unroll
    for (int k = 0; k < DD; k += 4) {
        float4 ws[4], wn[4];
#pragma unroll
        for (int q = 0; q < 4; q++) {
            ws[q] = *(const float4*)&Ws_s[(tj + 32 * q) * WPAD + k];
            wn[q] = *(const float4*)&Wn_s[(tj + 32 * q) * WPAD + k];
        }
#pragma unroll
        for (int i = 0; i < 4; i++) {
            float4 x = *(const float4*)&Xs[(4 * tn + i) * DD + k];
            float4 h = *(const float4*)&Hs[(4 * tn + i) * DD + k];
#pragma unroll
            for (int q = 0; q < 4; q++) {
                acc[i][q] += x.x * ws[q].x + x.y * ws[q].y + x.z * ws[q].z + x.w * ws[q].w;
                acc[i][q] += h.x * wn[q].x + h.y * wn[q].y + h.z * wn[q].z + h.w * wn[q].w;
            }
        }
    }
#pragma unroll
    for (int i = 0; i < 4; i++) {
        int r = r0 + 4 * tn + i;
        if (r < NN) {
#pragma unroll
            for (int q = 0; q < 4; q++)
                out[(size_t)r * DD + tj + 32 * q] = acc[i][q];
        }
    }
}

// ---------------- launch ----------------
extern "C" void kernel_launch(void* const* d_in, const int* in_sizes, int n_in,
                              void* d_out, int out_size) {
    const float* feat   = (const float*)d_in[0];
    const int*   src    = (const int*)d_in[1];
    const int*   dst    = (const int*)d_in[2];
    const float* gamma  = (const float*)d_in[3];
    const float* beta   = (const float*)d_in[4];
    const float* W_ih   = (const float*)d_in[5];
    const float* W_hh   = (const float*)d_in[6];
    const float* b_ih   = (const float*)d_in[7];
    const float* b_hh   = (const float*)d_in[8];
    const float* W_self = (const float*)d_in[9];
    const float* W_neigh= (const float*)d_in[10];
    float* out = (float*)d_out;

    const int smA = (TD * WPAD + 32 * DD) * 4;
    const int smG = (TD * WPAD + 32 * WPAD) * 4 + (64 + 32 + 32) * 4;
    const int smO = (2 * DD * WPAD + 2 * 32 * DD) * 4;
    cudaFuncSetAttribute(gemm384_k, cudaFuncAttributeMaxDynamicSharedMemorySize, smA);
    cudaFuncSetAttribute(gru_mma_k, cudaFuncAttributeMaxDynamicSharedMemorySize, smG);
    cudaFuncSetAttribute(out_k,     cudaFuncAttributeMaxDynamicSharedMemorySize, smO);

    const int NB = (NN + 31) / 32;

    bn_partial_k<<<BN_BLOCKS, DD>>>(feat);
    bn_final_k<<<1, DD>>>(gamma);
    normalize_k<<<(NN * DD / 4 + 255) / 256, 256>>>(feat, beta);
    clear_k<<<(NN + 255) / 256, 256>>>();
    scatter_k<<<(EE + 255) / 256, 256>>>(src, dst);
    nodesort_k<<<(NN + 7) / 8, 256>>>();
    scan_k<<<1, 1>>>();
    place_k<<<(NN + 255) / 256, 256>>>();
    gemm384_k<<<NB, 256, smA>>>(W_ih, b_ih);
    gru_mma_k<<<GRU_BLOCKS, 256, smG>>>(W_hh, b_hh);
    out_k<<<NB, 256, smO>>>(W_self, W_neigh, out);
}

// round 5
// speedup vs baseline: 3.1677x; 1.0528x over previous
#include <cuda_runtime.h>
#include <cstdint>

#define NN 50000
#define DD 128
#define EE 800000
#define TD 384
#define MAXDEG 48
#define CAP 64
#define BN_BLOCKS 512
#define BN_CHUNK 98
#define WPAD 132        // stride ≡ 4 (mod 32): conflict-free mma fragment LDS
#define APAD 260        // K=256 + 4
#define GNODES 32
#define GRU_BLOCKS ((NN + GNODES - 1) / GNODES)   // 1563

// ---------------- scratch (static device memory; no allocations) ----------------
__device__ float g_X[NN * DD];
__device__ float g_G[(size_t)NN * TD];
__device__ float g_Hn[NN * DD];
__device__ float g_part[2 * BN_BLOCKS * DD];
__device__ float g_mu[DD];
__device__ float g_scale[DD];
__device__ int   g_deg[NN];
__device__ unsigned long long g_keys[(size_t)NN * CAP];
__device__ int   g_neigh[NN * MAXDEG];
__device__ int   g_len[NN];
__device__ int   g_order[NN];
__device__ int   g_hist[MAXDEG + 1];
__device__ int   g_cursor[MAXDEG + 1];

// ---------------- helpers ----------------
__device__ __forceinline__ float tf32r(float x) {
    uint32_t r;
    asm("cvt.rna.tf32.f32 %0, %1;" : "=r"(r) : "f"(x));
    return __uint_as_float(r);
}
__device__ __forceinline__ void mma8(float* c, const uint32_t* a, const uint32_t* b) {
    asm volatile(
        "mma.sync.aligned.m16n8k8.row.col.f32.tf32.tf32.f32 "
        "{%0,%1,%2,%3},{%4,%5,%6,%7},{%8,%9},{%0,%1,%2,%3};"
        : "+f"(c[0]), "+f"(c[1]), "+f"(c[2]), "+f"(c[3])
        : "r"(a[0]), "r"(a[1]), "r"(a[2]), "r"(a[3]), "r"(b[0]), "r"(b[1]));
}
__device__ __forceinline__ float fast_tanh(float x) {
    float t;
    asm("tanh.approx.f32 %0, %1;" : "=f"(t) : "f"(x));
    return t;
}
__device__ __forceinline__ float fast_sigmoid(float x) {
    return 0.5f * fast_tanh(0.5f * x) + 0.5f;
}

// ---------------- BatchNorm ----------------
__global__ void bn_partial_k(const float* __restrict__ feat) {
    int b = blockIdx.x, d = threadIdx.x;
    int r0 = b * BN_CHUNK;
    int r1 = r0 + BN_CHUNK; if (r1 > NN) r1 = NN;
    float s = 0.f, ss = 0.f;
    for (int r = r0; r < r1; r++) {
        float v = feat[(size_t)r * DD + d];
        s += v; ss += v * v;
    }
    g_part[b * DD + d] = s;
    g_part[BN_BLOCKS * DD + b * DD + d] = ss;
}

__global__ void bn_final_k(const float* __restrict__ gamma) {
    int d = threadIdx.x;
    float s = 0.f, ss = 0.f;
    for (int b = 0; b < BN_BLOCKS; b++) {
        s  += g_part[b * DD + d];
        ss += g_part[BN_BLOCKS * DD + b * DD + d];
    }
    float mu = s / (float)NN;
    float var = ss / (float)NN - mu * mu;
    g_mu[d] = mu;
    g_scale[d] = rsqrtf(var + 1e-5f) * gamma[d];
}

__global__ void normalize_k(const float* __restrict__ feat, const float* __restrict__ beta) {
    int idx = blockIdx.x * blockDim.x + threadIdx.x;
    if (idx >= NN * DD / 4) return;
    float4 f = ((const float4*)feat)[idx];
    int d = (idx * 4) & (DD - 1);
    float4 o;
    o.x = (f.x - g_mu[d + 0]) * g_scale[d + 0] + beta[d + 0];
    o.y = (f.y - g_mu[d + 1]) * g_scale[d + 1] + beta[d + 1];
    o.z = (f.z - g_mu[d + 2]) * g_scale[d + 2] + beta[d + 2];
    o.w = (f.w - g_mu[d + 3]) * g_scale[d + 3] + beta[d + 3];
    ((float4*)g_X)[idx] = o;
}

// ---------------- adjacency build ----------------
__global__ void clear_k() {
    int i = blockIdx.x * blockDim.x + threadIdx.x;
    if (i < NN) g_deg[i] = 0;
    if (i <= MAXDEG) g_hist[i] = 0;
}

__global__ void scatter_k(const int* __restrict__ src, const int* __restrict__ dst) {
    int e = blockIdx.x * blockDim.x + threadIdx.x;
    if (e >= EE) return;
    int d = dst[e];
    if ((unsigned)d >= NN) return;
    int slot = atomicAdd(&g_deg[d], 1);
    if (slot < CAP)
        g_keys[(size_t)d * CAP + slot] = ((unsigned long long)e << 32) | (unsigned)src[e];
}

__global__ void nodesort_k() {
    __shared__ unsigned long long buf[8][CAP];
    int lane = threadIdx.x & 31;
    int w = threadIdx.x >> 5;
    int node = blockIdx.x * 8 + w;
    if (node >= NN) return;
    int deg = g_deg[node];
    int L = deg < CAP ? deg : CAP;
    if (lane < L)      buf[w][lane]      = g_keys[(size_t)node * CAP + lane];
    if (lane + 32 < L) buf[w][lane + 32] = g_keys[(size_t)node * CAP + lane + 32];
    __syncwarp();
    for (int m = 0; m < 2; m++) {
        int idx = lane + 32 * m;
        if (idx < L) {
            unsigned long long key = buf[w][idx];
            int rank = 0;
            for (int i = 0; i < L; i++) rank += (buf[w][i] < key);
            if (rank < MAXDEG)
                g_neigh[node * MAXDEG + rank] = (int)(unsigned)(key & 0xffffffffull);
        }
    }
    if (lane == 0) {
        int len = deg < MAXDEG ? deg : MAXDEG;
        g_len[node] = len;
        atomicAdd(&g_hist[len], 1);
    }
}

__global__ void scan_k() {
    int running = 0;
    for (int l = MAXDEG; l >= 0; l--) {
        g_cursor[l] = running;
        running += g_hist[l];
    }
}

__global__ void place_k() {
    int n = blockIdx.x * blockDim.x + threadIdx.x;
    if (n >= NN) return;
    int l = g_len[n];
    int pos = atomicAdd(&g_cursor[l], 1);
    g_order[pos] = n;
}

// ---------------- G = X @ W_ih^T + b_ih via mma tf32 ----------------
// 32 rows / block, 256 threads (8 warps). Warp w owns dims [16w,16w+16) of each gate.
__global__ __launch_bounds__(256, 1) void gemm384_k(const float* __restrict__ W,
                                                    const float* __restrict__ bias) {
    extern __shared__ float sm[];
    float* W_s = sm;                          // [384][WPAD]
    float* A_s = sm + TD * WPAD;              // [32][WPAD]
    int tid = threadIdx.x, lane = tid & 31, w = tid >> 5;
    int g2 = lane >> 2, t4 = lane & 3;
    int dbase = w * 16;
    int r0b = blockIdx.x * 32;

    for (int i = tid; i < TD * DD; i += 256) {
        int n = i >> 7, k = i & 127;
        W_s[n * WPAD + k] = tf32r(W[i]);
    }
    for (int i = tid; i < 32 * DD; i += 256) {
        int r = r0b + (i >> 7);
        A_s[(i >> 7) * WPAD + (i & 127)] = (r < NN) ? tf32r(g_X[(size_t)r * DD + (i & 127)]) : 0.f;
    }
    __syncthreads();

    float bb[3][2][2];
#pragma unroll
    for (int g = 0; g < 3; g++)
#pragma unroll
        for (int dt = 0; dt < 2; dt++) {
            int D0 = g * 128 + dbase + 8 * dt + 2 * t4;
            bb[g][dt][0] = bias[D0];
            bb[g][dt][1] = bias[D0 + 1];
        }
    float cacc[3][2][2][4];
#pragma unroll
    for (int g = 0; g < 3; g++)
#pragma unroll
        for (int mt = 0; mt < 2; mt++)
#pragma unroll
            for (int dt = 0; dt < 2; dt++) {
                cacc[g][mt][dt][0] = bb[g][dt][0];
                cacc[g][mt][dt][1] = bb[g][dt][1];
                cacc[g][mt][dt][2] = bb[g][dt][0];
                cacc[g][mt][dt][3] = bb[g][dt][1];
            }

    const uint32_t* As = (const uint32_t*)A_s;
    const uint32_t* Ws = (const uint32_t*)W_s;
#pragma unroll
    for (int kk = 0; kk < 16; kk++) {
        int c0 = kk * 8 + t4;
        uint32_t am[2][4];
#pragma unroll
        for (int mt = 0; mt < 2; mt++) {
            int r0 = 16 * mt + g2;
            am[mt][0] = As[r0 * WPAD + c0];
            am[mt][1] = As[(r0 + 8) * WPAD + c0];
            am[mt][2] = As[r0 * WPAD + c0 + 4];
            am[mt][3] = As[(r0 + 8) * WPAD + c0 + 4];
        }
        uint32_t bf[3][2][2];
#pragma unroll
        for (int g = 0; g < 3; g++)
#pragma unroll
            for (int dt = 0; dt < 2; dt++) {
                int n = g * 128 + dbase + 8 * dt + g2;
                bf[g][dt][0] = Ws[n * WPAD + c0];
                bf[g][dt][1] = Ws[n * WPAD + c0 + 4];
            }
#pragma unroll
        for (int g = 0; g < 3; g++)
#pragma unroll
            for (int mt = 0; mt < 2; mt++)
#pragma unroll
                for (int dt = 0; dt < 2; dt++)
                    mma8(cacc[g][mt][dt], am[mt], bf[g][dt]);
    }

#pragma unroll
    for (int mt = 0; mt < 2; mt++)
#pragma unroll
        for (int rr = 0; rr < 2; rr++) {
            int r = r0b + 16 * mt + g2 + 8 * rr;
            if (r < NN) {
#pragma unroll
                for (int g = 0; g < 3; g++)
#pragma unroll
                    for (int dt = 0; dt < 2; dt++) {
                        int D0 = g * 128 + dbase + 8 * dt + 2 * t4;
                        *(float2*)&g_G[(size_t)r * TD + D0] =
                            make_float2(cacc[g][mt][dt][rr * 2], cacc[g][mt][dt][rr * 2 + 1]);
                    }
            }
        }
}

// ---------------- GRU recurrence via mma.sync tf32 ----------------
__global__ __launch_bounds__(256, 1) void gru_mma_k(const float* __restrict__ Whh,
                                                    const float* __restrict__ bhh) {
    extern __shared__ float sm[];
    float* W_s = sm;                         // 384*WPAD
    float* H_s = sm + 384 * WPAD;            // 32*WPAD
    int*   s_s   = (int*)(H_s + 32 * WPAD);  // [2][32]
    int*   nid_s = s_s + 64;                 // [32]
    int*   len_s = nid_s + 32;               // [32]

    int tid = threadIdx.x, lane = tid & 31, w = tid >> 5;
    int g2 = lane >> 2, t4 = lane & 3;
    int dbase = w * 16;
    int base = blockIdx.x * GNODES;

    for (int i = tid; i < TD * DD; i += 256) {
        int n = i >> 7, k = i & 127;
        W_s[n * WPAD + k] = tf32r(Whh[i]);
    }
    for (int i = tid; i < 32 * WPAD; i += 256) H_s[i] = 0.f;
    if (tid < GNODES) {
        int gi = base + tid;
        int nid = (gi < NN) ? g_order[gi] : -1;
        nid_s[tid] = nid;
        len_s[tid] = (nid >= 0) ? g_len[nid] : 0;
    }
    __syncthreads();

    int maxlen = len_s[0];
    int lenR[2][2], nidR[2][2];
#pragma unroll
    for (int mt = 0; mt < 2; mt++)
#pragma unroll
        for (int rr = 0; rr < 2; rr++) {
            int r = 16 * mt + g2 + 8 * rr;
            lenR[mt][rr] = len_s[r];
            nidR[mt][rr] = nid_s[r];
        }
    float bb[3][2][2];
#pragma unroll
    for (int g = 0; g < 3; g++)
#pragma unroll
        for (int dt = 0; dt < 2; dt++) {
            int D0 = g * 128 + dbase + 8 * dt + 2 * t4;
            bb[g][dt][0] = bhh[D0];
            bb[g][dt][1] = bhh[D0 + 1];
        }
    float ho[2][2][4];
#pragma unroll
    for (int mt = 0; mt < 2; mt++)
#pragma unroll
        for (int dt = 0; dt < 2; dt++)
#pragma unroll
            for (int c = 0; c < 4; c++) ho[mt][dt][c] = 0.f;

    if (tid < GNODES)
        s_s[tid] = (0 < len_s[tid]) ? g_neigh[nid_s[tid] * MAXDEG] : 0;
    __syncthreads();

    const uint32_t* Hs = (const uint32_t*)H_s;
    const uint32_t* Ws = (const uint32_t*)W_s;

    for (int t = 0; t < maxlen; t++) {
        float2 gf[2][2][2][3];
#pragma unroll
        for (int mt = 0; mt < 2; mt++)
#pragma unroll
            for (int rr = 0; rr < 2; rr++) {
                int s = s_s[(t & 1) * 32 + 16 * mt + g2 + 8 * rr];
                const float* Gp = g_G + (size_t)s * TD;
#pragma unroll
                for (int dt = 0; dt < 2; dt++) {
                    int D0 = dbase + 8 * dt + 2 * t4;
#pragma unroll
                    for (int g = 0; g < 3; g++)
                        gf[mt][rr][dt][g] = *(const float2*)(Gp + g * 128 + D0);
                }
            }

        float cacc[3][2][2][4];
#pragma unroll
        for (int g = 0; g < 3; g++)
#pragma unroll
            for (int mt = 0; mt < 2; mt++)
#pragma unroll
                for (int dt = 0; dt < 2; dt++) {
                    cacc[g][mt][dt][0] = bb[g][dt][0];
                    cacc[g][mt][dt][1] = bb[g][dt][1];
                    cacc[g][mt][dt][2] = bb[g][dt][0];
                    cacc[g][mt][dt][3] = bb[g][dt][1];
                }

#pragma unroll
        for (int kk = 0; kk < 16; kk++) {
            int c0 = kk * 8 + t4;
            uint32_t am[2][4];
#pragma unroll
            for (int mt = 0; mt < 2; mt++) {
                int r0 = 16 * mt + g2;
                am[mt][0] = Hs[r0 * WPAD + c0];
                am[mt][1] = Hs[(r0 + 8) * WPAD + c0];
                am[mt][2] = Hs[r0 * WPAD + c0 + 4];
                am[mt][3] = Hs[(r0 + 8) * WPAD + c0 + 4];
            }
            uint32_t bf[3][2][2];
#pragma unroll
            for (int g = 0; g < 3; g++)
#pragma unroll
                for (int dt = 0; dt < 2; dt++) {
                    int n = g * 128 + dbase + 8 * dt + g2;
                    bf[g][dt][0] = Ws[n * WPAD + c0];
                    bf[g][dt][1] = Ws[n * WPAD + c0 + 4];
                }
#pragma unroll
            for (int g = 0; g < 3; g++)
#pragma unroll
                for (int mt = 0; mt < 2; mt++)
#pragma unroll
                    for (int dt = 0; dt < 2; dt++)
                        mma8(cacc[g][mt][dt], am[mt], bf[g][dt]);
        }
        __syncthreads();

#pragma unroll
        for (int mt = 0; mt < 2; mt++)
#pragma unroll
            for (int rr = 0; rr < 2; rr++) {
                bool act = (t < lenR[mt][rr]);
                int R = 16 * mt + g2 + 8 * rr;
#pragma unroll
                for (int dt = 0; dt < 2; dt++) {
#pragma unroll
                    for (int e = 0; e < 2; e++) {
                        int c = rr * 2 + e;
                        float gr = e ? gf[mt][rr][dt][0].y : gf[mt][rr][dt][0].x;
                        float gz = e ? gf[mt][rr][dt][1].y : gf[mt][rr][dt][1].x;
                        float gn = e ? gf[mt][rr][dt][2].y : gf[mt][rr][dt][2].x;
                        float r  = fast_sigmoid(gr + cacc[0][mt][dt][c]);
                        float z  = fast_sigmoid(gz + cacc[1][mt][dt][c]);
                        float nl = fast_tanh(gn + r * cacc[2][mt][dt][c]);
                        float hnew = (1.f - z) * nl + z * ho[mt][dt][c];
                        if (act) ho[mt][dt][c] = hnew;
                    }
                    int D0 = dbase + 8 * dt + 2 * t4;
                    *(float2*)&H_s[R * WPAD + D0] =
                        make_float2(tf32r(ho[mt][dt][rr * 2]), tf32r(ho[mt][dt][rr * 2 + 1]));
                }
            }
        if (tid < GNODES) {
            int tt = t + 1;
            s_s[(tt & 1) * 32 + tid] =
                (tt < len_s[tid]) ? g_neigh[nid_s[tid] * MAXDEG + tt] : 0;
        }
        __syncthreads();
    }

#pragma unroll
    for (int mt = 0; mt < 2; mt++)
#pragma unroll
        for (int rr = 0; rr < 2; rr++) {
            int nid = nidR[mt][rr];
            if (nid >= 0) {
#pragma unroll
                for (int dt = 0; dt < 2; dt++) {
                    int D0 = dbase + 8 * dt + 2 * t4;
                    *(float2*)&g_Hn[(size_t)nid * DD + D0] =
                        make_float2(ho[mt][dt][rr * 2], ho[mt][dt][rr * 2 + 1]);
                }
            }
        }
}

// ---------------- out = [X|Hn] @ [W_self|W_neigh]^T via mma tf32 (K=256) ----------------
// 32 rows / block, 8 warps; warp w owns out dims [16w, 16w+16).
__global__ __launch_bounds__(256, 1) void out_k(const float* __restrict__ Wself,
                                                const float* __restrict__ Wneigh,
                                                float* __restrict__ out) {
    extern __shared__ float sm[];
    float* W_s = sm;                          // [128][APAD]
    float* A_s = sm + DD * APAD;              // [32][APAD]
    int tid = threadIdx.x, lane = tid & 31, w = tid >> 5;
    int g2 = lane >> 2, t4 = lane & 3;
    int dbase = w * 16;
    int r0b = blockIdx.x * 32;

    // W_s[o][k] : k<128 -> Wself[o][k], else Wneigh[o][k-128]
    for (int i = tid; i < DD * 256; i += 256) {
        int o = i >> 8, k = i & 255;
        float v = (k < 128) ? Wself[o * DD + k] : Wneigh[o * DD + (k - 128)];
        W_s[o * APAD + k] = tf32r(v);
    }
    // A_s[r][k] : k<128 -> X, else Hn
    for (int i = tid; i < 32 * 256; i += 256) {
        int rl = i >> 8, k = i & 255;
        int r = r0b + rl;
        float v = 0.f;
        if (r < NN)
            v = (k < 128) ? g_X[(size_t)r * DD + k] : g_Hn[(size_t)r * DD + (k - 128)];
        A_s[rl * APAD + k] = tf32r(v);
    }
    __syncthreads();

    float cacc[2][2][4];
#pragma unroll
    for (int mt = 0; mt < 2; mt++)
#pragma unroll
        for (int dt = 0; dt < 2; dt++)
#pragma unroll
            for (int c = 0; c < 4; c++) cacc[mt][dt][c] = 0.f;

    const uint32_t* As = (const uint32_t*)A_s;
    const uint32_t* Ws = (const uint32_t*)W_s;
#pragma unroll
    for (int kk = 0; kk < 32; kk++) {
        int c0 = kk * 8 + t4;
        uint32_t am[2][4];
#pragma unroll
        for (int mt = 0; mt < 2; mt++) {
            int r0 = 16 * mt + g2;
            am[mt][0] = As[r0 * APAD + c0];
            am[mt][1] = As[(r0 + 8) * APAD + c0];
            am[mt][2] = As[r0 * APAD + c0 + 4];
            am[mt][3] = As[(r0 + 8) * APAD + c0 + 4];
        }
        uint32_t bf[2][2];
#pragma unroll
        for (int dt = 0; dt < 2; dt++) {
            int n = dbase + 8 * dt + g2;
            bf[dt][0] = Ws[n * APAD + c0];
            bf[dt][1] = Ws[n * APAD + c0 + 4];
        }
#pragma unroll
        for (int mt = 0; mt < 2; mt++)
#pragma unroll
            for (int dt = 0; dt < 2; dt++)
                mma8(cacc[mt][dt], am[mt], bf[dt]);
    }

#pragma unroll
    for (int mt = 0; mt < 2; mt++)
#pragma unroll
        for (int rr = 0; rr < 2; rr++) {
            int r = r0b + 16 * mt + g2 + 8 * rr;
            if (r < NN) {
#pragma unroll
                for (int dt = 0; dt < 2; dt++) {
                    int D0 = dbase + 8 * dt + 2 * t4;
                    *(float2*)&out[(size_t)r * DD + D0] =
                        make_float2(cacc[mt][dt][rr * 2], cacc[mt][dt][rr * 2 + 1]);
                }
            }
        }
}

// ---------------- launch ----------------
extern "C" void kernel_launch(void* const* d_in, const int* in_sizes, int n_in,
                              void* d_out, int out_size) {
    const float* feat   = (const float*)d_in[0];
    const int*   src    = (const int*)d_in[1];
    const int*   dst    = (const int*)d_in[2];
    const float* gamma  = (const float*)d_in[3];
    const float* beta   = (const float*)d_in[4];
    const float* W_ih   = (const float*)d_in[5];
    const float* W_hh   = (const float*)d_in[6];
    const float* b_ih   = (const float*)d_in[7];
    const float* b_hh   = (const float*)d_in[8];
    const float* W_self = (const float*)d_in[9];
    const float* W_neigh= (const float*)d_in[10];
    float* out = (float*)d_out;

    const int smA = (TD * WPAD + 32 * WPAD) * 4;
    const int smG = (TD * WPAD + 32 * WPAD) * 4 + (64 + 32 + 32) * 4;
    const int smO = (DD * APAD + 32 * APAD) * 4;
    cudaFuncSetAttribute(gemm384_k, cudaFuncAttributeMaxDynamicSharedMemorySize, smA);
    cudaFuncSetAttribute(gru_mma_k, cudaFuncAttributeMaxDynamicSharedMemorySize, smG);
    cudaFuncSetAttribute(out_k,     cudaFuncAttributeMaxDynamicSharedMemorySize, smO);

    const int NB = (NN + 31) / 32;

    bn_partial_k<<<BN_BLOCKS, DD>>>(feat);
    bn_final_k<<<1, DD>>>(gamma);
    normalize_k<<<(NN * DD / 4 + 255) / 256, 256>>>(feat, beta);
    clear_k<<<(NN + 255) / 256, 256>>>();
    scatter_k<<<(EE + 255) / 256, 256>>>(src, dst);
    nodesort_k<<<(NN + 7) / 8, 256>>>();
    scan_k<<<1, 1>>>();
    place_k<<<(NN + 255) / 256, 256>>>();
    gemm384_k<<<NB, 256, smA>>>(W_ih, b_ih);
    gru_mma_k<<<GRU_BLOCKS, 256, smG>>>(W_hh, b_hh);
    out_k<<<NB, 256, smO>>>(W_self, W_neigh, out);
}

// round 7
// speedup vs baseline: 3.3784x; 1.0665x over previous
#include <cuda_runtime.h>
#include <cstdint>

#define NN 50000
#define DD 128
#define EE 800000
#define TD 384
#define MAXDEG 48
#define CAP 64
#define BN_BLOCKS 512
#define BN_CHUNK 98
#define WPAD 132        // stride ≡ 4 (mod 32): conflict-free mma fragment LDS (gemm384)
#define APAD 260        // K=256 + 4 (out_k)
#define GNODES 64
#define GRU_BLOCKS ((NN + GNODES - 1) / GNODES)   // 782

// ---------------- scratch (static device memory; no allocations) ----------------
__device__ float g_X[NN * DD];
__device__ float g_G[(size_t)NN * TD];
__device__ float g_Hn[NN * DD];
__device__ float g_part[2 * BN_BLOCKS * DD];
__device__ float g_mu[DD];
__device__ float g_scale[DD];
__device__ int   g_deg[NN];
__device__ unsigned long long g_keys[(size_t)NN * CAP];
__device__ int   g_neigh[NN * MAXDEG];
__device__ int   g_len[NN];
__device__ int   g_order[NN];
__device__ int   g_hist[MAXDEG + 1];
__device__ int   g_cursor[MAXDEG + 1];

// ---------------- helpers ----------------
__device__ __forceinline__ float tf32r(float x) {
    uint32_t r;
    asm("cvt.rna.tf32.f32 %0, %1;" : "=r"(r) : "f"(x));
    return __uint_as_float(r);
}
__device__ __forceinline__ void mma8(float* c, const uint32_t* a, const uint32_t* b) {
    asm volatile(
        "mma.sync.aligned.m16n8k8.row.col.f32.tf32.tf32.f32 "
        "{%0,%1,%2,%3},{%4,%5,%6,%7},{%8,%9},{%0,%1,%2,%3};"
        : "+f"(c[0]), "+f"(c[1]), "+f"(c[2]), "+f"(c[3])
        : "r"(a[0]), "r"(a[1]), "r"(a[2]), "r"(a[3]), "r"(b[0]), "r"(b[1]));
}
__device__ __forceinline__ float fast_tanh(float x) {
    float t;
    asm("tanh.approx.f32 %0, %1;" : "=f"(t) : "f"(x));
    return t;
}
__device__ __forceinline__ float fast_sigmoid(float x) {
    return 0.5f * fast_tanh(0.5f * x) + 0.5f;
}

// ---------------- BatchNorm ----------------
__global__ void bn_partial_k(const float* __restrict__ feat) {
    int b = blockIdx.x, d = threadIdx.x;
    int r0 = b * BN_CHUNK;
    int r1 = r0 + BN_CHUNK; if (r1 > NN) r1 = NN;
    float s = 0.f, ss = 0.f;
    for (int r = r0; r < r1; r++) {
        float v = feat[(size_t)r * DD + d];
        s += v; ss += v * v;
    }
    g_part[b * DD + d] = s;
    g_part[BN_BLOCKS * DD + b * DD + d] = ss;
}

__global__ void bn_final_k(const float* __restrict__ gamma) {
    int d = threadIdx.x;
    float s = 0.f, ss = 0.f;
    for (int b = 0; b < BN_BLOCKS; b++) {
        s  += g_part[b * DD + d];
        ss += g_part[BN_BLOCKS * DD + b * DD + d];
    }
    float mu = s / (float)NN;
    float var = ss / (float)NN - mu * mu;
    g_mu[d] = mu;
    g_scale[d] = rsqrtf(var + 1e-5f) * gamma[d];
}

__global__ void normalize_k(const float* __restrict__ feat, const float* __restrict__ beta) {
    int idx = blockIdx.x * blockDim.x + threadIdx.x;
    if (idx >= NN * DD / 4) return;
    float4 f = ((const float4*)feat)[idx];
    int d = (idx * 4) & (DD - 1);
    float4 o;
    o.x = (f.x - g_mu[d + 0]) * g_scale[d + 0] + beta[d + 0];
    o.y = (f.y - g_mu[d + 1]) * g_scale[d + 1] + beta[d + 1];
    o.z = (f.z - g_mu[d + 2]) * g_scale[d + 2] + beta[d + 2];
    o.w = (f.w - g_mu[d + 3]) * g_scale[d + 3] + beta[d + 3];
    ((float4*)g_X)[idx] = o;
}

// ---------------- adjacency build ----------------
__global__ void clear_k() {
    int i = blockIdx.x * blockDim.x + threadIdx.x;
    if (i < NN) g_deg[i] = 0;
    if (i <= MAXDEG) g_hist[i] = 0;
}

__global__ void scatter_k(const int* __restrict__ src, const int* __restrict__ dst) {
    int e = blockIdx.x * blockDim.x + threadIdx.x;
    if (e >= EE) return;
    int d = dst[e];
    if ((unsigned)d >= NN) return;
    int slot = atomicAdd(&g_deg[d], 1);
    if (slot < CAP)
        g_keys[(size_t)d * CAP + slot] = ((unsigned long long)e << 32) | (unsigned)src[e];
}

__global__ void nodesort_k() {
    __shared__ unsigned long long buf[8][CAP];
    int lane = threadIdx.x & 31;
    int w = threadIdx.x >> 5;
    int node = blockIdx.x * 8 + w;
    if (node >= NN) return;
    int deg = g_deg[node];
    int L = deg < CAP ? deg : CAP;
    if (lane < L)      buf[w][lane]      = g_keys[(size_t)node * CAP + lane];
    if (lane + 32 < L) buf[w][lane + 32] = g_keys[(size_t)node * CAP + lane + 32];
    __syncwarp();
    for (int m = 0; m < 2; m++) {
        int idx = lane + 32 * m;
        if (idx < L) {
            unsigned long long key = buf[w][idx];
            int rank = 0;
            for (int i = 0; i < L; i++) rank += (buf[w][i] < key);
            if (rank < MAXDEG)
                g_neigh[node * MAXDEG + rank] = (int)(unsigned)(key & 0xffffffffull);
        }
    }
    if (lane == 0) {
        int len = deg < MAXDEG ? deg : MAXDEG;
        g_len[node] = len;
        atomicAdd(&g_hist[len], 1);
    }
}

__global__ void scan_k() {
    int running = 0;
    for (int l = MAXDEG; l >= 0; l--) {
        g_cursor[l] = running;
        running += g_hist[l];
    }
}

__global__ void place_k() {
    int n = blockIdx.x * blockDim.x + threadIdx.x;
    if (n >= NN) return;
    int l = g_len[n];
    int pos = atomicAdd(&g_cursor[l], 1);
    g_order[pos] = n;
}

// ---------------- G = X @ W_ih^T + b_ih via mma tf32 ----------------
__global__ __launch_bounds__(256, 1) void gemm384_k(const float* __restrict__ W,
                                                    const float* __restrict__ bias) {
    extern __shared__ float sm[];
    float* W_s = sm;                          // [384][WPAD]
    float* A_s = sm + TD * WPAD;              // [32][WPAD]
    int tid = threadIdx.x, lane = tid & 31, w = tid >> 5;
    int g2 = lane >> 2, t4 = lane & 3;
    int dbase = w * 16;
    int r0b = blockIdx.x * 32;

    for (int i = tid; i < TD * DD; i += 256) {
        int n = i >> 7, k = i & 127;
        W_s[n * WPAD + k] = tf32r(W[i]);
    }
    for (int i = tid; i < 32 * DD; i += 256) {
        int r = r0b + (i >> 7);
        A_s[(i >> 7) * WPAD + (i & 127)] = (r < NN) ? tf32r(g_X[(size_t)r * DD + (i & 127)]) : 0.f;
    }
    __syncthreads();

    float bb[3][2][2];
#pragma unroll
    for (int g = 0; g < 3; g++)
#pragma unroll
        for (int dt = 0; dt < 2; dt++) {
            int D0 = g * 128 + dbase + 8 * dt + 2 * t4;
            bb[g][dt][0] = bias[D0];
            bb[g][dt][1] = bias[D0 + 1];
        }
    float cacc[3][2][2][4];
#pragma unroll
    for (int g = 0; g < 3; g++)
#pragma unroll
        for (int mt = 0; mt < 2; mt++)
#pragma unroll
            for (int dt = 0; dt < 2; dt++) {
                cacc[g][mt][dt][0] = bb[g][dt][0];
                cacc[g][mt][dt][1] = bb[g][dt][1];
                cacc[g][mt][dt][2] = bb[g][dt][0];
                cacc[g][mt][dt][3] = bb[g][dt][1];
            }

    const uint32_t* As = (const uint32_t*)A_s;
    const uint32_t* Ws = (const uint32_t*)W_s;
#pragma unroll
    for (int kk = 0; kk < 16; kk++) {
        int c0 = kk * 8 + t4;
        uint32_t am[2][4];
#pragma unroll
        for (int mt = 0; mt < 2; mt++) {
            int r0 = 16 * mt + g2;
            am[mt][0] = As[r0 * WPAD + c0];
            am[mt][1] = As[(r0 + 8) * WPAD + c0];
            am[mt][2] = As[r0 * WPAD + c0 + 4];
            am[mt][3] = As[(r0 + 8) * WPAD + c0 + 4];
        }
        uint32_t bf[3][2][2];
#pragma unroll
        for (int g = 0; g < 3; g++)
#pragma unroll
            for (int dt = 0; dt < 2; dt++) {
                int n = g * 128 + dbase + 8 * dt + g2;
                bf[g][dt][0] = Ws[n * WPAD + c0];
                bf[g][dt][1] = Ws[n * WPAD + c0 + 4];
            }
#pragma unroll
        for (int g = 0; g < 3; g++)
#pragma unroll
            for (int mt = 0; mt < 2; mt++)
#pragma unroll
                for (int dt = 0; dt < 2; dt++)
                    mma8(cacc[g][mt][dt], am[mt], bf[g][dt]);
    }

#pragma unroll
    for (int mt = 0; mt < 2; mt++)
#pragma unroll
        for (int rr = 0; rr < 2; rr++) {
            int r = r0b + 16 * mt + g2 + 8 * rr;
            if (r < NN) {
#pragma unroll
                for (int g = 0; g < 3; g++)
#pragma unroll
                    for (int dt = 0; dt < 2; dt++) {
                        int D0 = g * 128 + dbase + 8 * dt + 2 * t4;
                        *(float2*)&g_G[(size_t)r * TD + D0] =
                            make_float2(cacc[g][mt][dt][rr * 2], cacc[g][mt][dt][rr * 2 + 1]);
                    }
            }
        }
}

// ---------------- GRU recurrence via mma.sync tf32, 64 nodes/CTA ----------------
// XOR-swizzled unpadded W_s [384][128] and H_s [64][128]:
//   phys(row, c) = row*128 + (c ^ ((row&7)<<2))
// All fragment accesses have row&7 == g2 -> bank = t4 + 4*g2 (conflict-free).
__global__ __launch_bounds__(256, 1) void gru_mma_k(const float* __restrict__ Whh,
                                                    const float* __restrict__ bhh) {
    extern __shared__ float sm[];
    float* W_s = sm;                          // 3*128*128 = 49152 floats
    float* H_s = sm + 49152;                  // 64*128 = 8192 floats
    int*   s_s   = (int*)(H_s + 8192);        // [2][64]
    int*   nid_s = s_s + 128;                 // [64]
    int*   len_s = nid_s + 64;                // [64]

    int tid = threadIdx.x, lane = tid & 31, w = tid >> 5;
    int g2 = lane >> 2, t4 = lane & 3;
    int cx = g2 << 2;
    int dbase = w * 16;
    int base = blockIdx.x * GNODES;

    for (int i = tid; i < 3 * 128 * 128; i += 256) {
        int n = i >> 7, k = i & 127;
        W_s[(n << 7) + (k ^ ((n & 7) << 2))] = tf32r(Whh[i]);
    }
    for (int i = tid; i < GNODES * 128; i += 256) H_s[i] = 0.f;
    if (tid < GNODES) {
        int gi = base + tid;
        int nid = (gi < NN) ? g_order[gi] : -1;
        nid_s[tid] = nid;
        len_s[tid] = (nid >= 0) ? g_len[nid] : 0;
    }
    __syncthreads();

    int maxlen = len_s[0];
    int lenR[4][2], nidR[4][2];
#pragma unroll
    for (int mt = 0; mt < 4; mt++)
#pragma unroll
        for (int rr = 0; rr < 2; rr++) {
            int R = 16 * mt + g2 + 8 * rr;
            lenR[mt][rr] = len_s[R];
            nidR[mt][rr] = nid_s[R];
        }
    float bb[3][2][2];
#pragma unroll
    for (int g = 0; g < 3; g++)
#pragma unroll
        for (int dt = 0; dt < 2; dt++) {
            int D0 = g * 128 + dbase + 8 * dt + 2 * t4;
            bb[g][dt][0] = bhh[D0];
            bb[g][dt][1] = bhh[D0 + 1];
        }
    float ho[4][2][4];
#pragma unroll
    for (int mt = 0; mt < 4; mt++)
#pragma unroll
        for (int dt = 0; dt < 2; dt++)
#pragma unroll
            for (int c = 0; c < 4; c++) ho[mt][dt][c] = 0.f;

    if (tid < GNODES)
        s_s[tid] = (0 < len_s[tid]) ? g_neigh[nid_s[tid] * MAXDEG] : 0;
    __syncthreads();

    const uint32_t* Hs = (const uint32_t*)H_s;
    const uint32_t* Ws = (const uint32_t*)W_s;

    for (int t = 0; t < maxlen; t++) {
        // ---- prefetch G for pass 0 (mt 0,1) ----
        float2 gf0[2][2][2][3];
#pragma unroll
        for (int m2 = 0; m2 < 2; m2++)
#pragma unroll
            for (int rr = 0; rr < 2; rr++) {
                int s = s_s[(t & 1) * 64 + 16 * m2 + g2 + 8 * rr];
                const float* Gp = g_G + (size_t)s * TD;
#pragma unroll
                for (int dt = 0; dt < 2; dt++) {
                    int D0 = dbase + 8 * dt + 2 * t4;
#pragma unroll
                    for (int g = 0; g < 3; g++)
                        gf0[m2][rr][dt][g] = *(const float2*)(Gp + g * 128 + D0);
                }
            }

        // ---- accumulators = b_hh ----
        float cacc[3][4][2][4];
#pragma unroll
        for (int g = 0; g < 3; g++)
#pragma unroll
            for (int mt = 0; mt < 4; mt++)
#pragma unroll
                for (int dt = 0; dt < 2; dt++) {
                    cacc[g][mt][dt][0] = bb[g][dt][0];
                    cacc[g][mt][dt][1] = bb[g][dt][1];
                    cacc[g][mt][dt][2] = bb[g][dt][0];
                    cacc[g][mt][dt][3] = bb[g][dt][1];
                }

        // ---- mma K-loop: M=64, N=384, K=128 ----
#pragma unroll
        for (int kk = 0; kk < 16; kk++) {
            int c0 = kk * 8 + t4;
            int ca = c0 ^ cx;
            int ca4 = (c0 + 4) ^ cx;
            uint32_t am[4][4];
#pragma unroll
            for (int mt = 0; mt < 4; mt++) {
                int r0 = (16 * mt + g2) << 7;
                int r1 = r0 + (8 << 7);
                am[mt][0] = Hs[r0 + ca];
                am[mt][1] = Hs[r1 + ca];
                am[mt][2] = Hs[r0 + ca4];
                am[mt][3] = Hs[r1 + ca4];
            }
            uint32_t bf[3][2][2];
#pragma unroll
            for (int g = 0; g < 3; g++)
#pragma unroll
                for (int dt = 0; dt < 2; dt++) {
                    int nb = (g * 128 + dbase + 8 * dt + g2) << 7;
                    bf[g][dt][0] = Ws[nb + ca];
                    bf[g][dt][1] = Ws[nb + ca4];
                }
#pragma unroll
            for (int g = 0; g < 3; g++)
#pragma unroll
                for (int mt = 0; mt < 4; mt++)
#pragma unroll
                    for (int dt = 0; dt < 2; dt++)
                        mma8(cacc[g][mt][dt], am[mt], bf[g][dt]);
        }
        __syncthreads();   // H_s reads complete

        // ---- issue G loads for pass 1 (mt 2,3) ----
        float2 gf1[2][2][2][3];
#pragma unroll
        for (int m2 = 0; m2 < 2; m2++)
#pragma unroll
            for (int rr = 0; rr < 2; rr++) {
                int s = s_s[(t & 1) * 64 + 16 * (m2 + 2) + g2 + 8 * rr];
                const float* Gp = g_G + (size_t)s * TD;
#pragma unroll
                for (int dt = 0; dt < 2; dt++) {
                    int D0 = dbase + 8 * dt + 2 * t4;
#pragma unroll
                    for (int g = 0; g < 3; g++)
                        gf1[m2][rr][dt][g] = *(const float2*)(Gp + g * 128 + D0);
                }
            }

        // ---- epilogue pass 0 (mt 0,1) then pass 1 (mt 2,3) ----
#pragma unroll
        for (int p = 0; p < 2; p++) {
#pragma unroll
            for (int m2 = 0; m2 < 2; m2++) {
                int mt = 2 * p + m2;
#pragma unroll
                for (int rr = 0; rr < 2; rr++) {
                    bool act = (t < lenR[mt][rr]);
                    int R = 16 * mt + g2 + 8 * rr;
#pragma unroll
                    for (int dt = 0; dt < 2; dt++) {
#pragma unroll
                        for (int e = 0; e < 2; e++) {
                            int c = rr * 2 + e;
                            float2 vr = p ? gf1[m2][rr][dt][0] : gf0[m2][rr][dt][0];
                            float2 vz = p ? gf1[m2][rr][dt][1] : gf0[m2][rr][dt][1];
                            float2 vn = p ? gf1[m2][rr][dt][2] : gf0[m2][rr][dt][2];
                            float gr = e ? vr.y : vr.x;
                            float gz = e ? vz.y : vz.x;
                            float gn = e ? vn.y : vn.x;
                            float r  = fast_sigmoid(gr + cacc[0][mt][dt][c]);
                            float z  = fast_sigmoid(gz + cacc[1][mt][dt][c]);
                            float nl = fast_tanh(gn + r * cacc[2][mt][dt][c]);
                            float hnew = (1.f - z) * nl + z * ho[mt][dt][c];
                            if (act) ho[mt][dt][c] = hnew;
                        }
                        int D0 = dbase + 8 * dt + 2 * t4;
                        *(float2*)&H_s[(R << 7) + (D0 ^ cx)] =
                            make_float2(tf32r(ho[mt][dt][rr * 2]), tf32r(ho[mt][dt][rr * 2 + 1]));
                    }
                }
            }
        }

        // stage src ids for t+1
        if (tid < GNODES) {
            int tt = t + 1;
            s_s[(tt & 1) * 64 + tid] =
                (tt < len_s[tid]) ? g_neigh[nid_s[tid] * MAXDEG + tt] : 0;
        }
        __syncthreads();
    }

    // ---- final hidden to gmem ----
#pragma unroll
    for (int mt = 0; mt < 4; mt++)
#pragma unroll
        for (int rr = 0; rr < 2; rr++) {
            int nid = nidR[mt][rr];
            if (nid >= 0) {
#pragma unroll
                for (int dt = 0; dt < 2; dt++) {
                    int D0 = dbase + 8 * dt + 2 * t4;
                    *(float2*)&g_Hn[(size_t)nid * DD + D0] =
                        make_float2(ho[mt][dt][rr * 2], ho[mt][dt][rr * 2 + 1]);
                }
            }
        }
}

// ---------------- out = [X|Hn] @ [W_self|W_neigh]^T via mma tf32 (K=256) ----------------
__global__ __launch_bounds__(256, 1) void out_k(const float* __restrict__ Wself,
                                                const float* __restrict__ Wneigh,
                                                float* __restrict__ out) {
    extern __shared__ float sm[];
    float* W_s = sm;                          // [128][APAD]
    float* A_s = sm + DD * APAD;              // [32][APAD]
    int tid = threadIdx.x, lane = tid & 31, w = tid >> 5;
    int g2 = lane >> 2, t4 = lane & 3;
    int dbase = w * 16;
    int r0b = blockIdx.x * 32;

    for (int i = tid; i < DD * 256; i += 256) {
        int o = i >> 8, k = i & 255;
        float v = (k < 128) ? Wself[o * DD + k] : Wneigh[o * DD + (k - 128)];
        W_s[o * APAD + k] = tf32r(v);
    }
    for (int i = tid; i < 32 * 256; i += 256) {
        int rl = i >> 8, k = i & 255;
        int r = r0b + rl;
        float v = 0.f;
        if (r < NN)
            v = (k < 128) ? g_X[(size_t)r * DD + k] : g_Hn[(size_t)r * DD + (k - 128)];
        A_s[rl * APAD + k] = tf32r(v);
    }
    __syncthreads();

    float cacc[2][2][4];
#pragma unroll
    for (int mt = 0; mt < 2; mt++)
#pragma unroll
        for (int dt = 0; dt < 2; dt++)
#pragma unroll
            for (int c = 0; c < 4; c++) cacc[mt][dt][c] = 0.f;

    const uint32_t* As = (const uint32_t*)A_s;
    const uint32_t* Ws = (const uint32_t*)W_s;
#pragma unroll
    for (int kk = 0; kk < 32; kk++) {
        int c0 = kk * 8 + t4;
        uint32_t am[2][4];
#pragma unroll
        for (int mt = 0; mt < 2; mt++) {
            int r0 = 16 * mt + g2;
            am[mt][0] = As[r0 * APAD + c0];
            am[mt][1] = As[(r0 + 8) * APAD + c0];
            am[mt][2] = As[r0 * APAD + c0 + 4];
            am[mt][3] = As[(r0 + 8) * APAD + c0 + 4];
        }
        uint32_t bf[2][2];
#pragma unroll
        for (int dt = 0; dt < 2; dt++) {
            int n = dbase + 8 * dt + g2;
            bf[dt][0] = Ws[n * APAD + c0];
            bf[dt][1] = Ws[n * APAD + c0 + 4];
        }
#pragma unroll
        for (int mt = 0; mt < 2; mt++)
#pragma unroll
            for (int dt = 0; dt < 2; dt++)
                mma8(cacc[mt][dt], am[mt], bf[dt]);
    }

#pragma unroll
    for (int mt = 0; mt < 2; mt++)
#pragma unroll
        for (int rr = 0; rr < 2; rr++) {
            int r = r0b + 16 * mt + g2 + 8 * rr;
            if (r < NN) {
#pragma unroll
                for (int dt = 0; dt < 2; dt++) {
                    int D0 = dbase + 8 * dt + 2 * t4;
                    *(float2*)&out[(size_t)r * DD + D0] =
                        make_float2(cacc[mt][dt][rr * 2], cacc[mt][dt][rr * 2 + 1]);
                }
            }
        }
}

// ---------------- launch ----------------
extern "C" void kernel_launch(void* const* d_in, const int* in_sizes, int n_in,
                              void* d_out, int out_size) {
    const float* feat   = (const float*)d_in[0];
    const int*   src    = (const int*)d_in[1];
    const int*   dst    = (const int*)d_in[2];
    const float* gamma  = (const float*)d_in[3];
    const float* beta   = (const float*)d_in[4];
    const float* W_ih   = (const float*)d_in[5];
    const float* W_hh   = (const float*)d_in[6];
    const float* b_ih   = (const float*)d_in[7];
    const float* b_hh   = (const float*)d_in[8];
    const float* W_self = (const float*)d_in[9];
    const float* W_neigh= (const float*)d_in[10];
    float* out = (float*)d_out;

    const int smA = (TD * WPAD + 32 * WPAD) * 4;
    const int smG = (3 * 128 * 128 + GNODES * 128 + 256) * 4;   // 230,400 B
    const int smO = (DD * APAD + 32 * APAD) * 4;
    cudaFuncSetAttribute(gemm384_k, cudaFuncAttributeMaxDynamicSharedMemorySize, smA);
    cudaFuncSetAttribute(gru_mma_k, cudaFuncAttributeMaxDynamicSharedMemorySize, smG);
    cudaFuncSetAttribute(out_k,     cudaFuncAttributeMaxDynamicSharedMemorySize, smO);

    const int NB = (NN + 31) / 32;

    bn_partial_k<<<BN_BLOCKS, DD>>>(feat);
    bn_final_k<<<1, DD>>>(gamma);
    normalize_k<<<(NN * DD / 4 + 255) / 256, 256>>>(feat, beta);
    clear_k<<<(NN + 255) / 256, 256>>>();
    scatter_k<<<(EE + 255) / 256, 256>>>(src, dst);
    nodesort_k<<<(NN + 7) / 8, 256>>>();
    scan_k<<<1, 1>>>();
    place_k<<<(NN + 255) / 256, 256>>>();
    gemm384_k<<<NB, 256, smA>>>(W_ih, b_ih);
    gru_mma_k<<<GRU_BLOCKS, 256, smG>>>(W_hh, b_hh);
    out_k<<<NB, 256, smO>>>(W_self, W_neigh, out);
}